// round 15
// baseline (speedup 1.0000x reference)
#include <cuda_runtime.h>
#include <cstdint>

// ---------------------------------------------------------------------------
// QBWBottleneck fp32 implicit-GEMM, f32x2 FMA (R11 skeleton), occupancy 3 (R15).
// Only change vs R11: __launch_bounds__(256, 3) -> <=85 regs, 3 CTAs/SM.
// Arithmetic values and order unchanged -> rel_err identical.
// ---------------------------------------------------------------------------

#define EPSBN 1e-5f
typedef unsigned long long u64;

__device__ float g_buf1[12845056];   // 51.4 MB
__device__ float g_buf2[3211264];    // 12.8 MB

__device__ __forceinline__ float fq(float y, float s) {
    float q = rintf(y / s);
    q = fminf(fmaxf(q, -127.f), 127.f);
    return q * s;
}

// ---- packed fp32x2 helpers -------------------------------------------------
__device__ __forceinline__ u64 packdup(float a) {
    u64 r;
    asm("mov.b64 %0, {%1, %1};" : "=l"(r) : "r"(__float_as_uint(a)));
    return r;
}
__device__ __forceinline__ u64 pack2(float lo, float hi) {
    u64 r;
    asm("mov.b64 %0, {%1, %2};" : "=l"(r) : "r"(__float_as_uint(lo)), "r"(__float_as_uint(hi)));
    return r;
}
__device__ __forceinline__ void fma2(u64& d, u64 a, u64 b) {
    asm("fma.rn.f32x2 %0, %1, %2, %0;" : "+l"(d) : "l"(a), "l"(b));
}
__device__ __forceinline__ float2 unpk(u64 v) {
    uint32_t lo, hi;
    asm("mov.b64 {%0, %1}, %2;" : "=r"(lo), "=r"(hi) : "l"(v));
    return make_float2(__uint_as_float(lo), __uint_as_float(hi));
}

// BM=BN=128, BK=16, 256 threads, 8x8 per thread (acc packed as 8x4 f32x2).
#define GEMM_COMPUTE_STEP()                                                    \
    __syncthreads();                                                           \
    _Pragma("unroll")                                                          \
    for (int kk = 0; kk < 16; ++kk) {                                          \
        float4 av0 = *(const float4*)&As[kk][ty * 8];                          \
        float4 av1 = *(const float4*)&As[kk][ty * 8 + 4];                      \
        float4 bv0 = *(const float4*)&Bs[kk][tx * 8];                          \
        float4 bv1 = *(const float4*)&Bs[kk][tx * 8 + 4];                      \
        u64 a2[8], b2[4];                                                      \
        a2[0] = packdup(av0.x); a2[1] = packdup(av0.y);                        \
        a2[2] = packdup(av0.z); a2[3] = packdup(av0.w);                        \
        a2[4] = packdup(av1.x); a2[5] = packdup(av1.y);                        \
        a2[6] = packdup(av1.z); a2[7] = packdup(av1.w);                        \
        b2[0] = pack2(bv0.x, bv0.y); b2[1] = pack2(bv0.z, bv0.w);              \
        b2[2] = pack2(bv1.x, bv1.y); b2[3] = pack2(bv1.z, bv1.w);              \
        _Pragma("unroll")                                                      \
        for (int i = 0; i < 8; ++i)                                            \
            _Pragma("unroll")                                                  \
            for (int j = 0; j < 4; ++j)                                        \
                fma2(acc2[i][j], a2[i], b2[j]);                                \
    }                                                                          \
    __syncthreads();

#define ACCV(i, j) (((j) & 1) ? unpk(acc2[(i)][(j) >> 1]).y                    \
                              : unpk(acc2[(i)][(j) >> 1]).x)

#define ACC_INIT()                                                             \
    u64 acc2[8][4];                                                            \
    _Pragma("unroll")                                                          \
    for (int i = 0; i < 8; ++i)                                                \
        _Pragma("unroll")                                                      \
        for (int j = 0; j < 4; ++j) acc2[i][j] = 0ull;

// ---------------------------------------------------------------------------
// Kernel 1: conv1 1x1 s1.  C[co=128][j=100352] = W1[128,256] * X[256, j]
// ---------------------------------------------------------------------------
__global__ __launch_bounds__(256, 3)
void conv1_k(const float* __restrict__ x, const float* __restrict__ w,
             const float* __restrict__ gg, const float* __restrict__ bb,
             const float* __restrict__ mm, const float* __restrict__ vv,
             const float* __restrict__ ss)
{
    __shared__ float As[16][128];
    __shared__ float Bs[16][128];
    const int t  = threadIdx.x;
    const int tx = t & 15, ty = t >> 4;
    const int jcol = t & 127, krow = t >> 7;
    const int jg = blockIdx.x * 128 + jcol;
    const int n  = jg / 3136, p = jg - n * 3136;
    const float* xb = x + n * 802816 + p;
    const int ai = t >> 1;
    const int ak = (t & 1) * 8;

    ACC_INIT();

    for (int k0 = 0; k0 < 256; k0 += 16) {
        const float* wp = w + ai * 256 + k0 + ak;
#pragma unroll
        for (int r = 0; r < 8; ++r) As[ak + r][ai] = wp[r];
        const float* xp = xb + (k0 + krow * 8) * 3136;
#pragma unroll
        for (int r = 0; r < 8; ++r) Bs[krow * 8 + r][jcol] = xp[r * 3136];
        GEMM_COMPUTE_STEP();
    }

    const float s = *ss;
    float inv_[8], bia_[8];
#pragma unroll
    for (int i = 0; i < 8; ++i) {
        int co = ty * 8 + i;
        float iv = gg[co] / sqrtf(vv[co] + EPSBN);
        inv_[i] = iv;
        bia_[i] = bb[co] - mm[co] * iv;
    }
#pragma unroll
    for (int j = 0; j < 8; ++j) {
        int jj = blockIdx.x * 128 + tx * 8 + j;
        int nn = jj / 3136, pp = jj - nn * 3136;
        float* op = g_buf1 + nn * 401408 + pp;
#pragma unroll
        for (int i = 0; i < 8; ++i) {
            float y = ACCV(i, j) * inv_[i] + bia_[i];
            op[(ty * 8 + i) * 3136] = fmaxf(fq(y, s), 0.f);
        }
    }
}

// ---------------------------------------------------------------------------
// Kernel 2: conv2 3x3 s2 pad1, 128->128. 9 accumulated 1x1-GEMM taps.
// ---------------------------------------------------------------------------
__global__ __launch_bounds__(256, 3)
void conv2_k(const float* __restrict__ w,
             const float* __restrict__ gg, const float* __restrict__ bb,
             const float* __restrict__ mm, const float* __restrict__ vv,
             const float* __restrict__ ss)
{
    __shared__ float As[16][128];
    __shared__ float Bs[16][128];
    const int t  = threadIdx.x;
    const int tx = t & 15, ty = t >> 4;
    const int jcol = t & 127, krow = t >> 7;
    const int jg = blockIdx.x * 128 + jcol;
    const int n  = jg / 784, p = jg - n * 784;
    const int ho = p / 28, wo = p - ho * 28;
    const int h0 = 2 * ho - 1, w0 = 2 * wo - 1;
    const float* o1n = g_buf1 + n * 401408;
    const int ai = t >> 1;
    const int ak = (t & 1) * 8;

    ACC_INIT();

    for (int tap = 0; tap < 9; ++tap) {
        const int kh = tap / 3, kw = tap - kh * 3;
        const int h = h0 + kh, wd = w0 + kw;
        const bool valid = ((unsigned)h < 56u) && ((unsigned)wd < 56u);
        const int off = h * 56 + wd;
        for (int k0 = 0; k0 < 128; k0 += 16) {
#pragma unroll
            for (int r = 0; r < 8; ++r)
                As[ak + r][ai] = w[(ai * 128 + k0 + ak + r) * 9 + tap];
#pragma unroll
            for (int r = 0; r < 8; ++r) {
                int k = k0 + krow * 8 + r;
                Bs[krow * 8 + r][jcol] = valid ? o1n[k * 3136 + off] : 0.f;
            }
            GEMM_COMPUTE_STEP();
        }
    }

    const float s = *ss;
    float inv_[8], bia_[8];
#pragma unroll
    for (int i = 0; i < 8; ++i) {
        int co = ty * 8 + i;
        float iv = gg[co] / sqrtf(vv[co] + EPSBN);
        inv_[i] = iv;
        bia_[i] = bb[co] - mm[co] * iv;
    }
#pragma unroll
    for (int j = 0; j < 8; ++j) {
        int jj = blockIdx.x * 128 + tx * 8 + j;
        int nn = jj / 784, pp = jj - nn * 784;
        float* op = g_buf2 + nn * 100352 + pp;
#pragma unroll
        for (int i = 0; i < 8; ++i) {
            float y = ACCV(i, j) * inv_[i] + bia_[i];
            op[(ty * 8 + i) * 784] = fmaxf(fq(y, s), 0.f);
        }
    }
}

// ---------------------------------------------------------------------------
// Kernel 3: conv3 1x1, 128->512, no relu. Writes fq values into g_buf1.
// ---------------------------------------------------------------------------
__global__ __launch_bounds__(256, 3)
void conv3_k(const float* __restrict__ w,
             const float* __restrict__ gg, const float* __restrict__ bb,
             const float* __restrict__ mm, const float* __restrict__ vv,
             const float* __restrict__ ss)
{
    __shared__ float As[16][128];
    __shared__ float Bs[16][128];
    const int t  = threadIdx.x;
    const int tx = t & 15, ty = t >> 4;
    const int jcol = t & 127, krow = t >> 7;
    const int coT = blockIdx.y * 128;
    const int jg = blockIdx.x * 128 + jcol;
    const int n  = jg / 784, p = jg - n * 784;
    const float* o2b = g_buf2 + n * 100352 + p;
    const int ai = t >> 1;
    const int ak = (t & 1) * 8;

    ACC_INIT();

    for (int k0 = 0; k0 < 128; k0 += 16) {
        const float* wp = w + (coT + ai) * 128 + k0 + ak;
#pragma unroll
        for (int r = 0; r < 8; ++r) As[ak + r][ai] = wp[r];
        const float* xp = o2b + (k0 + krow * 8) * 784;
#pragma unroll
        for (int r = 0; r < 8; ++r) Bs[krow * 8 + r][jcol] = xp[r * 784];
        GEMM_COMPUTE_STEP();
    }

    const float s = *ss;
    float inv_[8], bia_[8];
#pragma unroll
    for (int i = 0; i < 8; ++i) {
        int co = coT + ty * 8 + i;
        float iv = gg[co] / sqrtf(vv[co] + EPSBN);
        inv_[i] = iv;
        bia_[i] = bb[co] - mm[co] * iv;
    }
#pragma unroll
    for (int j = 0; j < 8; ++j) {
        int jj = blockIdx.x * 128 + tx * 8 + j;
        int nn = jj / 784, pp = jj - nn * 784;
        float* op = g_buf1 + nn * 401408 + (coT + ty * 8) * 784 + pp;
#pragma unroll
        for (int i = 0; i < 8; ++i) {
            float y = ACCV(i, j) * inv_[i] + bia_[i];
            op[i * 784] = fq(y, s);
        }
    }
}

// ---------------------------------------------------------------------------
// Kernel 4: shortcut 1x1 s2, 256->512, fq; out = relu(t3 + sc).
// ---------------------------------------------------------------------------
__global__ __launch_bounds__(256, 3)
void conv4_k(const float* __restrict__ x, const float* __restrict__ w,
             const float* __restrict__ gg, const float* __restrict__ bb,
             const float* __restrict__ mm, const float* __restrict__ vv,
             const float* __restrict__ ss, float* __restrict__ out)
{
    __shared__ float As[16][128];
    __shared__ float Bs[16][128];
    const int t  = threadIdx.x;
    const int tx = t & 15, ty = t >> 4;
    const int jcol = t & 127, krow = t >> 7;
    const int coT = blockIdx.y * 128;
    const int jg = blockIdx.x * 128 + jcol;
    const int n  = jg / 784, p = jg - n * 784;
    const int ho = p / 28, wo = p - ho * 28;
    const float* xb = x + n * 802816 + (2 * ho) * 56 + 2 * wo;
    const int ai = t >> 1;
    const int ak = (t & 1) * 8;

    ACC_INIT();

    for (int k0 = 0; k0 < 256; k0 += 16) {
        const float* wp = w + (coT + ai) * 256 + k0 + ak;
#pragma unroll
        for (int r = 0; r < 8; ++r) As[ak + r][ai] = wp[r];
        const float* xp = xb + (k0 + krow * 8) * 3136;
#pragma unroll
        for (int r = 0; r < 8; ++r) Bs[krow * 8 + r][jcol] = xp[r * 3136];
        GEMM_COMPUTE_STEP();
    }

    const float s = *ss;
    float inv_[8], bia_[8];
#pragma unroll
    for (int i = 0; i < 8; ++i) {
        int co = coT + ty * 8 + i;
        float iv = gg[co] / sqrtf(vv[co] + EPSBN);
        inv_[i] = iv;
        bia_[i] = bb[co] - mm[co] * iv;
    }
#pragma unroll
    for (int j = 0; j < 8; ++j) {
        int jj = blockIdx.x * 128 + tx * 8 + j;
        int nn = jj / 784, pp = jj - nn * 784;
        int base = nn * 401408 + (coT + ty * 8) * 784 + pp;
        const float* t3 = g_buf1 + base;
        float* op = out + base;
#pragma unroll
        for (int i = 0; i < 8; ++i) {
            float y  = ACCV(i, j) * inv_[i] + bia_[i];
            float qs = fq(y, s);
            op[i * 784] = fmaxf(t3[i * 784] + qs, 0.f);
        }
    }
}

// ---------------------------------------------------------------------------
extern "C" void kernel_launch(void* const* d_in, const int* in_sizes, int n_in,
                              void* d_out, int out_size)
{
    const float* x  = (const float*)d_in[0];
    const float* w1 = (const float*)d_in[1];
    const float* g1 = (const float*)d_in[2];
    const float* b1 = (const float*)d_in[3];
    const float* m1 = (const float*)d_in[4];
    const float* v1 = (const float*)d_in[5];
    const float* s1 = (const float*)d_in[6];
    const float* w2 = (const float*)d_in[7];
    const float* g2 = (const float*)d_in[8];
    const float* b2 = (const float*)d_in[9];
    const float* m2 = (const float*)d_in[10];
    const float* v2 = (const float*)d_in[11];
    const float* s2 = (const float*)d_in[12];
    const float* w3 = (const float*)d_in[13];
    const float* g3 = (const float*)d_in[14];
    const float* b3 = (const float*)d_in[15];
    const float* m3 = (const float*)d_in[16];
    const float* v3 = (const float*)d_in[17];
    const float* s3 = (const float*)d_in[18];
    const float* ws = (const float*)d_in[19];
    const float* gs = (const float*)d_in[20];
    const float* bs = (const float*)d_in[21];
    const float* ms = (const float*)d_in[22];
    const float* vs = (const float*)d_in[23];
    const float* ss = (const float*)d_in[24];

    conv1_k<<<784, 256>>>(x, w1, g1, b1, m1, v1, s1);
    conv2_k<<<196, 256>>>(w2, g2, b2, m2, v2, s2);
    conv3_k<<<dim3(196, 4), 256>>>(w3, g3, b3, m3, v3, s3);
    conv4_k<<<dim3(196, 4), 256>>>(x, ws, gs, bs, ms, vs, ss, (float*)d_out);
}

// round 16
// speedup vs baseline: 1.4821x; 1.4821x over previous
#include <cuda_runtime.h>
#include <cstdint>

// ---------------------------------------------------------------------------
// QBWBottleneck fp32 implicit-GEMM, f32x2 FMA (R11 skeleton) + conv3/conv4
// fusion via smem t3 tile (R16). Arithmetic identical to R11.
//
//  conv1 1x1 s1 256->128 +BN+fq+relu  -> g_buf1 [32,128,56,56]
//  conv2 3x3 s2 128->128 +BN+fq+relu  -> g_buf2 [32,128,28,28]
//  conv34 fused: t3 = fq(conv3) staged in smem; out = relu(t3 + fq(sc))
// ---------------------------------------------------------------------------

#define EPSBN 1e-5f
typedef unsigned long long u64;

__device__ float g_buf1[12845056];   // 51.4 MB
__device__ float g_buf2[3211264];    // 12.8 MB

__device__ __forceinline__ float fq(float y, float s) {
    float q = rintf(y / s);
    q = fminf(fmaxf(q, -127.f), 127.f);
    return q * s;
}

// ---- packed fp32x2 helpers -------------------------------------------------
__device__ __forceinline__ u64 packdup(float a) {
    u64 r;
    asm("mov.b64 %0, {%1, %1};" : "=l"(r) : "r"(__float_as_uint(a)));
    return r;
}
__device__ __forceinline__ u64 pack2(float lo, float hi) {
    u64 r;
    asm("mov.b64 %0, {%1, %2};" : "=l"(r) : "r"(__float_as_uint(lo)), "r"(__float_as_uint(hi)));
    return r;
}
__device__ __forceinline__ void fma2(u64& d, u64 a, u64 b) {
    asm("fma.rn.f32x2 %0, %1, %2, %0;" : "+l"(d) : "l"(a), "l"(b));
}
__device__ __forceinline__ float2 unpk(u64 v) {
    uint32_t lo, hi;
    asm("mov.b64 {%0, %1}, %2;" : "=r"(lo), "=r"(hi) : "l"(v));
    return make_float2(__uint_as_float(lo), __uint_as_float(hi));
}

// BM=BN=128, BK=16, 256 threads, 8x8 per thread (acc packed as 8x4 f32x2).
#define GEMM_COMPUTE_STEP(As, Bs)                                              \
    __syncthreads();                                                           \
    _Pragma("unroll")                                                          \
    for (int kk = 0; kk < 16; ++kk) {                                          \
        float4 av0 = *(const float4*)&(As)[kk * 128 + ty * 8];                 \
        float4 av1 = *(const float4*)&(As)[kk * 128 + ty * 8 + 4];             \
        float4 bv0 = *(const float4*)&(Bs)[kk * 128 + tx * 8];                 \
        float4 bv1 = *(const float4*)&(Bs)[kk * 128 + tx * 8 + 4];             \
        u64 a2[8], b2[4];                                                      \
        a2[0] = packdup(av0.x); a2[1] = packdup(av0.y);                        \
        a2[2] = packdup(av0.z); a2[3] = packdup(av0.w);                        \
        a2[4] = packdup(av1.x); a2[5] = packdup(av1.y);                        \
        a2[6] = packdup(av1.z); a2[7] = packdup(av1.w);                        \
        b2[0] = pack2(bv0.x, bv0.y); b2[1] = pack2(bv0.z, bv0.w);              \
        b2[2] = pack2(bv1.x, bv1.y); b2[3] = pack2(bv1.z, bv1.w);              \
        _Pragma("unroll")                                                      \
        for (int i = 0; i < 8; ++i)                                            \
            _Pragma("unroll")                                                  \
            for (int j = 0; j < 4; ++j)                                        \
                fma2(acc2[i][j], a2[i], b2[j]);                                \
    }                                                                          \
    __syncthreads();

#define ACCV(i, j) (((j) & 1) ? unpk(acc2[(i)][(j) >> 1]).y                    \
                              : unpk(acc2[(i)][(j) >> 1]).x)

#define ACC_INIT()                                                             \
    _Pragma("unroll")                                                          \
    for (int i = 0; i < 8; ++i)                                                \
        _Pragma("unroll")                                                      \
        for (int j = 0; j < 4; ++j) acc2[i][j] = 0ull;

// ---------------------------------------------------------------------------
// Kernel 1: conv1 1x1 s1 (unchanged from R11).
// ---------------------------------------------------------------------------
__global__ __launch_bounds__(256, 2)
void conv1_k(const float* __restrict__ x, const float* __restrict__ w,
             const float* __restrict__ gg, const float* __restrict__ bb,
             const float* __restrict__ mm, const float* __restrict__ vv,
             const float* __restrict__ ss)
{
    __shared__ float As[16 * 128];
    __shared__ float Bs[16 * 128];
    const int t  = threadIdx.x;
    const int tx = t & 15, ty = t >> 4;
    const int jcol = t & 127, krow = t >> 7;
    const int jg = blockIdx.x * 128 + jcol;
    const int n  = jg / 3136, p = jg - n * 3136;
    const float* xb = x + n * 802816 + p;
    const int ai = t >> 1;
    const int ak = (t & 1) * 8;

    u64 acc2[8][4];
    ACC_INIT();

    for (int k0 = 0; k0 < 256; k0 += 16) {
        const float* wp = w + ai * 256 + k0 + ak;
#pragma unroll
        for (int r = 0; r < 8; ++r) As[(ak + r) * 128 + ai] = wp[r];
        const float* xp = xb + (k0 + krow * 8) * 3136;
#pragma unroll
        for (int r = 0; r < 8; ++r) Bs[(krow * 8 + r) * 128 + jcol] = xp[r * 3136];
        GEMM_COMPUTE_STEP(As, Bs);
    }

    const float s = *ss;
    float inv_[8], bia_[8];
#pragma unroll
    for (int i = 0; i < 8; ++i) {
        int co = ty * 8 + i;
        float iv = gg[co] / sqrtf(vv[co] + EPSBN);
        inv_[i] = iv;
        bia_[i] = bb[co] - mm[co] * iv;
    }
#pragma unroll
    for (int j = 0; j < 8; ++j) {
        int jj = blockIdx.x * 128 + tx * 8 + j;
        int nn = jj / 3136, pp = jj - nn * 3136;
        float* op = g_buf1 + nn * 401408 + pp;
#pragma unroll
        for (int i = 0; i < 8; ++i) {
            float y = ACCV(i, j) * inv_[i] + bia_[i];
            op[(ty * 8 + i) * 3136] = fmaxf(fq(y, s), 0.f);
        }
    }
}

// ---------------------------------------------------------------------------
// Kernel 2: conv2 3x3 s2 pad1 (unchanged from R11).
// ---------------------------------------------------------------------------
__global__ __launch_bounds__(256, 2)
void conv2_k(const float* __restrict__ w,
             const float* __restrict__ gg, const float* __restrict__ bb,
             const float* __restrict__ mm, const float* __restrict__ vv,
             const float* __restrict__ ss)
{
    __shared__ float As[16 * 128];
    __shared__ float Bs[16 * 128];
    const int t  = threadIdx.x;
    const int tx = t & 15, ty = t >> 4;
    const int jcol = t & 127, krow = t >> 7;
    const int jg = blockIdx.x * 128 + jcol;
    const int n  = jg / 784, p = jg - n * 784;
    const int ho = p / 28, wo = p - ho * 28;
    const int h0 = 2 * ho - 1, w0 = 2 * wo - 1;
    const float* o1n = g_buf1 + n * 401408;
    const int ai = t >> 1;
    const int ak = (t & 1) * 8;

    u64 acc2[8][4];
    ACC_INIT();

    for (int tap = 0; tap < 9; ++tap) {
        const int kh = tap / 3, kw = tap - kh * 3;
        const int h = h0 + kh, wd = w0 + kw;
        const bool valid = ((unsigned)h < 56u) && ((unsigned)wd < 56u);
        const int off = h * 56 + wd;
        for (int k0 = 0; k0 < 128; k0 += 16) {
#pragma unroll
            for (int r = 0; r < 8; ++r)
                As[(ak + r) * 128 + ai] = w[(ai * 128 + k0 + ak + r) * 9 + tap];
#pragma unroll
            for (int r = 0; r < 8; ++r) {
                int k = k0 + krow * 8 + r;
                Bs[(krow * 8 + r) * 128 + jcol] = valid ? o1n[k * 3136 + off] : 0.f;
            }
            GEMM_COMPUTE_STEP(As, Bs);
        }
    }

    const float s = *ss;
    float inv_[8], bia_[8];
#pragma unroll
    for (int i = 0; i < 8; ++i) {
        int co = ty * 8 + i;
        float iv = gg[co] / sqrtf(vv[co] + EPSBN);
        inv_[i] = iv;
        bia_[i] = bb[co] - mm[co] * iv;
    }
#pragma unroll
    for (int j = 0; j < 8; ++j) {
        int jj = blockIdx.x * 128 + tx * 8 + j;
        int nn = jj / 784, pp = jj - nn * 784;
        float* op = g_buf2 + nn * 100352 + pp;
#pragma unroll
        for (int i = 0; i < 8; ++i) {
            float y = ACCV(i, j) * inv_[i] + bia_[i];
            op[(ty * 8 + i) * 784] = fmaxf(fq(y, s), 0.f);
        }
    }
}

// ---------------------------------------------------------------------------
// Kernel 34: fused conv3 (1x1 128->512, fq) + conv4 (shortcut 1x1 s2 256->512,
// fq) + add + relu. t3 tile staged in dynamic smem (never touches HBM).
// grid (196, 4). Dynamic smem: As(8KB) Bs(8KB) t3s(128*129*4 = 66048B).
// ---------------------------------------------------------------------------
#define SM34 (16 * 128 * 4 * 2 + 128 * 129 * 4)   // 82432 bytes

__global__ __launch_bounds__(256, 2)
void conv34_k(const float* __restrict__ x,
              const float* __restrict__ w3,
              const float* __restrict__ g3, const float* __restrict__ b3,
              const float* __restrict__ m3, const float* __restrict__ v3,
              const float* __restrict__ s3p,
              const float* __restrict__ ws,
              const float* __restrict__ gs, const float* __restrict__ bs,
              const float* __restrict__ ms, const float* __restrict__ vs,
              const float* __restrict__ ssp,
              float* __restrict__ out)
{
    extern __shared__ float dsm[];
    float* As  = dsm;                 // [16][128]
    float* Bs  = dsm + 2048;          // [16][128]
    float* t3s = dsm + 4096;          // [128 j][129] (padded)

    const int t  = threadIdx.x;
    const int tx = t & 15, ty = t >> 4;
    const int jcol = t & 127, krow = t >> 7;
    const int coT = blockIdx.y * 128;
    const int jg = blockIdx.x * 128 + jcol;
    const int n  = jg / 784, p = jg - n * 784;
    const int ho = p / 28, wo = p - ho * 28;
    const float* o2b = g_buf2 + n * 100352 + p;
    const float* xb  = x + n * 802816 + (2 * ho) * 56 + 2 * wo;
    const int ai = t >> 1;
    const int ak = (t & 1) * 8;

    u64 acc2[8][4];

    // ---------------- Phase A: conv3 (K = 128) ----------------
    ACC_INIT();
    for (int k0 = 0; k0 < 128; k0 += 16) {
        const float* wp = w3 + (coT + ai) * 128 + k0 + ak;
#pragma unroll
        for (int r = 0; r < 8; ++r) As[(ak + r) * 128 + ai] = wp[r];
        const float* xp = o2b + (k0 + krow * 8) * 784;
#pragma unroll
        for (int r = 0; r < 8; ++r) Bs[(krow * 8 + r) * 128 + jcol] = xp[r * 784];
        GEMM_COMPUTE_STEP(As, Bs);
    }
    {
        const float s3 = *s3p;
        float inv_[8], bia_[8];
#pragma unroll
        for (int i = 0; i < 8; ++i) {
            int co = coT + ty * 8 + i;
            float iv = g3[co] / sqrtf(v3[co] + EPSBN);
            inv_[i] = iv;
            bia_[i] = b3[co] - m3[co] * iv;
        }
#pragma unroll
        for (int j = 0; j < 8; ++j)
#pragma unroll
            for (int i = 0; i < 8; ++i) {
                float y = ACCV(i, j) * inv_[i] + bia_[i];
                t3s[(tx * 8 + j) * 129 + ty * 8 + i] = fq(y, s3);
            }
    }
    __syncthreads();   // t3s complete before phase B overwrites As/Bs usage

    // ---------------- Phase B: conv4 shortcut (K = 256) ----------------
    ACC_INIT();
    for (int k0 = 0; k0 < 256; k0 += 16) {
        const float* wp = ws + (coT + ai) * 256 + k0 + ak;
#pragma unroll
        for (int r = 0; r < 8; ++r) As[(ak + r) * 128 + ai] = wp[r];
        const float* xp = xb + (k0 + krow * 8) * 3136;
#pragma unroll
        for (int r = 0; r < 8; ++r) Bs[(krow * 8 + r) * 128 + jcol] = xp[r * 3136];
        GEMM_COMPUTE_STEP(As, Bs);
    }
    {
        const float s = *ssp;
        float inv_[8], bia_[8];
#pragma unroll
        for (int i = 0; i < 8; ++i) {
            int co = coT + ty * 8 + i;
            float iv = gs[co] / sqrtf(vs[co] + EPSBN);
            inv_[i] = iv;
            bia_[i] = bs[co] - ms[co] * iv;
        }
#pragma unroll
        for (int j = 0; j < 8; ++j) {
            int jj = blockIdx.x * 128 + tx * 8 + j;
            int nn = jj / 784, pp = jj - nn * 784;
            float* op = out + nn * 401408 + (coT + ty * 8) * 784 + pp;
#pragma unroll
            for (int i = 0; i < 8; ++i) {
                float y  = ACCV(i, j) * inv_[i] + bia_[i];
                float qs = fq(y, s);
                float t3 = t3s[(tx * 8 + j) * 129 + ty * 8 + i];
                op[i * 784] = fmaxf(t3 + qs, 0.f);
            }
        }
    }
}

// ---------------------------------------------------------------------------
extern "C" void kernel_launch(void* const* d_in, const int* in_sizes, int n_in,
                              void* d_out, int out_size)
{
    const float* x  = (const float*)d_in[0];
    const float* w1 = (const float*)d_in[1];
    const float* g1 = (const float*)d_in[2];
    const float* b1 = (const float*)d_in[3];
    const float* m1 = (const float*)d_in[4];
    const float* v1 = (const float*)d_in[5];
    const float* s1 = (const float*)d_in[6];
    const float* w2 = (const float*)d_in[7];
    const float* g2 = (const float*)d_in[8];
    const float* b2 = (const float*)d_in[9];
    const float* m2 = (const float*)d_in[10];
    const float* v2 = (const float*)d_in[11];
    const float* s2 = (const float*)d_in[12];
    const float* w3 = (const float*)d_in[13];
    const float* g3 = (const float*)d_in[14];
    const float* b3 = (const float*)d_in[15];
    const float* m3 = (const float*)d_in[16];
    const float* v3 = (const float*)d_in[17];
    const float* s3 = (const float*)d_in[18];
    const float* ws = (const float*)d_in[19];
    const float* gs = (const float*)d_in[20];
    const float* bs = (const float*)d_in[21];
    const float* ms = (const float*)d_in[22];
    const float* vs = (const float*)d_in[23];
    const float* ss = (const float*)d_in[24];

    static int inited = 0;
    if (!inited) {
        cudaFuncSetAttribute(conv34_k, cudaFuncAttributeMaxDynamicSharedMemorySize, SM34);
        inited = 1;
    }

    conv1_k<<<784, 256>>>(x, w1, g1, b1, m1, v1, s1);
    conv2_k<<<196, 256>>>(w2, g2, b2, m2, v2, s2);
    conv34_k<<<dim3(196, 4), 256, SM34>>>(x, w3, g3, b3, m3, v3, s3,
                                          ws, gs, bs, ms, vs, ss, (float*)d_out);
}

// round 17
// speedup vs baseline: 1.6988x; 1.1462x over previous
#include <cuda_runtime.h>
#include <cstdint>

// ---------------------------------------------------------------------------
// QBWBottleneck fp32 implicit-GEMM, f32x2 FMA, conv3/4 fused, u8 level
// inter-stage storage (R17). Arithmetic bit-identical to R11/R16:
// stored level k, reconstructed (float)k * s == previously stored fl(k*s).
// ---------------------------------------------------------------------------

#define EPSBN 1e-5f
typedef unsigned long long u64;
typedef unsigned char u8;

__device__ u8 g_buf1u[12845056];   // o1 levels [n][128][3136], 12.9 MB
__device__ u8 g_buf2u[3211264];    // o2 levels [n][128][784],  3.2 MB

__device__ __forceinline__ float fq(float y, float s) {
    float q = rintf(y / s);
    q = fminf(fmaxf(q, -127.f), 127.f);
    return q * s;
}
__device__ __forceinline__ float fql(float y, float s) {   // clipped level
    return fminf(fmaxf(rintf(y / s), -127.f), 127.f);
}

// ---- packed fp32x2 helpers -------------------------------------------------
__device__ __forceinline__ u64 packdup(float a) {
    u64 r;
    asm("mov.b64 %0, {%1, %1};" : "=l"(r) : "r"(__float_as_uint(a)));
    return r;
}
__device__ __forceinline__ u64 pack2(float lo, float hi) {
    u64 r;
    asm("mov.b64 %0, {%1, %2};" : "=l"(r) : "r"(__float_as_uint(lo)), "r"(__float_as_uint(hi)));
    return r;
}
__device__ __forceinline__ void fma2(u64& d, u64 a, u64 b) {
    asm("fma.rn.f32x2 %0, %1, %2, %0;" : "+l"(d) : "l"(a), "l"(b));
}
__device__ __forceinline__ float2 unpk(u64 v) {
    uint32_t lo, hi;
    asm("mov.b64 {%0, %1}, %2;" : "=r"(lo), "=r"(hi) : "l"(v));
    return make_float2(__uint_as_float(lo), __uint_as_float(hi));
}

// BM=BN=128, BK=16, 256 threads, 8x8 per thread (acc packed as 8x4 f32x2).
#define GEMM_COMPUTE_STEP(As, Bs)                                              \
    __syncthreads();                                                           \
    _Pragma("unroll")                                                          \
    for (int kk = 0; kk < 16; ++kk) {                                          \
        float4 av0 = *(const float4*)&(As)[kk * 128 + ty * 8];                 \
        float4 av1 = *(const float4*)&(As)[kk * 128 + ty * 8 + 4];             \
        float4 bv0 = *(const float4*)&(Bs)[kk * 128 + tx * 8];                 \
        float4 bv1 = *(const float4*)&(Bs)[kk * 128 + tx * 8 + 4];             \
        u64 a2[8], b2[4];                                                      \
        a2[0] = packdup(av0.x); a2[1] = packdup(av0.y);                        \
        a2[2] = packdup(av0.z); a2[3] = packdup(av0.w);                        \
        a2[4] = packdup(av1.x); a2[5] = packdup(av1.y);                        \
        a2[6] = packdup(av1.z); a2[7] = packdup(av1.w);                        \
        b2[0] = pack2(bv0.x, bv0.y); b2[1] = pack2(bv0.z, bv0.w);              \
        b2[2] = pack2(bv1.x, bv1.y); b2[3] = pack2(bv1.z, bv1.w);              \
        _Pragma("unroll")                                                      \
        for (int i = 0; i < 8; ++i)                                            \
            _Pragma("unroll")                                                  \
            for (int j = 0; j < 4; ++j)                                        \
                fma2(acc2[i][j], a2[i], b2[j]);                                \
    }                                                                          \
    __syncthreads();

#define ACCV(i, j) (((j) & 1) ? unpk(acc2[(i)][(j) >> 1]).y                    \
                              : unpk(acc2[(i)][(j) >> 1]).x)

#define ACC_INIT()                                                             \
    _Pragma("unroll")                                                          \
    for (int i = 0; i < 8; ++i)                                                \
        _Pragma("unroll")                                                      \
        for (int j = 0; j < 4; ++j) acc2[i][j] = 0ull;

// vectorized contiguous A load: 8 floats via 2x LDG.128, transposed STS
#define LOAD_A_VEC(As, ptr)                                                    \
    {                                                                          \
        float4 w0 = *(const float4*)(ptr);                                     \
        float4 w1 = *(const float4*)((ptr) + 4);                               \
        (As)[(ak + 0) * 128 + ai] = w0.x; (As)[(ak + 1) * 128 + ai] = w0.y;    \
        (As)[(ak + 2) * 128 + ai] = w0.z; (As)[(ak + 3) * 128 + ai] = w0.w;    \
        (As)[(ak + 4) * 128 + ai] = w1.x; (As)[(ak + 5) * 128 + ai] = w1.y;    \
        (As)[(ak + 6) * 128 + ai] = w1.z; (As)[(ak + 7) * 128 + ai] = w1.w;    \
    }

// ---------------------------------------------------------------------------
// Kernel 1: conv1 1x1 s1. Output stored as u8 levels.
// ---------------------------------------------------------------------------
__global__ __launch_bounds__(256, 2)
void conv1_k(const float* __restrict__ x, const float* __restrict__ w,
             const float* __restrict__ gg, const float* __restrict__ bb,
             const float* __restrict__ mm, const float* __restrict__ vv,
             const float* __restrict__ ss)
{
    __shared__ float As[16 * 128];
    __shared__ float Bs[16 * 128];
    const int t  = threadIdx.x;
    const int tx = t & 15, ty = t >> 4;
    const int jcol = t & 127, krow = t >> 7;
    const int jg = blockIdx.x * 128 + jcol;
    const int n  = jg / 3136, p = jg - n * 3136;
    const float* xb = x + n * 802816 + p;
    const int ai = t >> 1;
    const int ak = (t & 1) * 8;

    u64 acc2[8][4];
    ACC_INIT();

    for (int k0 = 0; k0 < 256; k0 += 16) {
        LOAD_A_VEC(As, w + ai * 256 + k0 + ak);
        const float* xp = xb + (k0 + krow * 8) * 3136;
#pragma unroll
        for (int r = 0; r < 8; ++r) Bs[(krow * 8 + r) * 128 + jcol] = xp[r * 3136];
        GEMM_COMPUTE_STEP(As, Bs);
    }

    const float s = *ss;
    float inv_[8], bia_[8];
#pragma unroll
    for (int i = 0; i < 8; ++i) {
        int co = ty * 8 + i;
        float iv = gg[co] / sqrtf(vv[co] + EPSBN);
        inv_[i] = iv;
        bia_[i] = bb[co] - mm[co] * iv;
    }
#pragma unroll
    for (int j = 0; j < 8; ++j) {
        int jj = blockIdx.x * 128 + tx * 8 + j;
        int nn = jj / 3136, pp = jj - nn * 3136;
        u8* op = g_buf1u + nn * 401408 + pp;
#pragma unroll
        for (int i = 0; i < 8; ++i) {
            float y = ACCV(i, j) * inv_[i] + bia_[i];
            float q = fmaxf(fql(y, s), 0.f);       // relu on level (s > 0)
            op[(ty * 8 + i) * 3136] = (u8)(int)q;
        }
    }
}

// ---------------------------------------------------------------------------
// Kernel 2: conv2 3x3 s2 pad1. B reconstructed from u8 levels * s1.
// Output stored as u8 levels.
// ---------------------------------------------------------------------------
__global__ __launch_bounds__(256, 2)
void conv2_k(const float* __restrict__ w,
             const float* __restrict__ gg, const float* __restrict__ bb,
             const float* __restrict__ mm, const float* __restrict__ vv,
             const float* __restrict__ ss, const float* __restrict__ sp)
{
    __shared__ float As[16 * 128];
    __shared__ float Bs[16 * 128];
    const int t  = threadIdx.x;
    const int tx = t & 15, ty = t >> 4;
    const int jcol = t & 127, krow = t >> 7;
    const int jg = blockIdx.x * 128 + jcol;
    const int n  = jg / 784, p = jg - n * 784;
    const int ho = p / 28, wo = p - ho * 28;
    const int h0 = 2 * ho - 1, w0 = 2 * wo - 1;
    const u8* o1n = g_buf1u + n * 401408;
    const int ai = t >> 1;
    const int ak = (t & 1) * 8;
    const float s1 = *sp;

    u64 acc2[8][4];
    ACC_INIT();

    for (int tap = 0; tap < 9; ++tap) {
        const int kh = tap / 3, kw = tap - kh * 3;
        const int h = h0 + kh, wd = w0 + kw;
        const bool valid = ((unsigned)h < 56u) && ((unsigned)wd < 56u);
        const int off = h * 56 + wd;
        for (int k0 = 0; k0 < 128; k0 += 16) {
#pragma unroll
            for (int r = 0; r < 8; ++r)
                As[(ak + r) * 128 + ai] = w[(ai * 128 + k0 + ak + r) * 9 + tap];
#pragma unroll
            for (int r = 0; r < 8; ++r) {
                int k = k0 + krow * 8 + r;
                Bs[(krow * 8 + r) * 128 + jcol] =
                    valid ? (float)o1n[k * 3136 + off] * s1 : 0.f;
            }
            GEMM_COMPUTE_STEP(As, Bs);
        }
    }

    const float s = *ss;
    float inv_[8], bia_[8];
#pragma unroll
    for (int i = 0; i < 8; ++i) {
        int co = ty * 8 + i;
        float iv = gg[co] / sqrtf(vv[co] + EPSBN);
        inv_[i] = iv;
        bia_[i] = bb[co] - mm[co] * iv;
    }
#pragma unroll
    for (int j = 0; j < 8; ++j) {
        int jj = blockIdx.x * 128 + tx * 8 + j;
        int nn = jj / 784, pp = jj - nn * 784;
        u8* op = g_buf2u + nn * 100352 + pp;
#pragma unroll
        for (int i = 0; i < 8; ++i) {
            float y = ACCV(i, j) * inv_[i] + bia_[i];
            float q = fmaxf(fql(y, s), 0.f);
            op[(ty * 8 + i) * 784] = (u8)(int)q;
        }
    }
}

// ---------------------------------------------------------------------------
// Kernel 34: fused conv3 + shortcut conv4 + add + relu (t3 in smem).
// conv3 B reconstructed from u8 levels * s2.
// ---------------------------------------------------------------------------
#define SM34 (16 * 128 * 4 * 2 + 128 * 129 * 4)   // 82432 bytes

__global__ __launch_bounds__(256, 2)
void conv34_k(const float* __restrict__ x,
              const float* __restrict__ w3,
              const float* __restrict__ g3, const float* __restrict__ b3,
              const float* __restrict__ m3, const float* __restrict__ v3,
              const float* __restrict__ s3p, const float* __restrict__ s2p,
              const float* __restrict__ ws,
              const float* __restrict__ gs, const float* __restrict__ bs,
              const float* __restrict__ ms, const float* __restrict__ vs,
              const float* __restrict__ ssp,
              float* __restrict__ out)
{
    extern __shared__ float dsm[];
    float* As  = dsm;                 // [16][128]
    float* Bs  = dsm + 2048;          // [16][128]
    float* t3s = dsm + 4096;          // [128 j][129]

    const int t  = threadIdx.x;
    const int tx = t & 15, ty = t >> 4;
    const int jcol = t & 127, krow = t >> 7;
    const int coT = blockIdx.y * 128;
    const int jg = blockIdx.x * 128 + jcol;
    const int n  = jg / 784, p = jg - n * 784;
    const int ho = p / 28, wo = p - ho * 28;
    const u8* o2b = g_buf2u + n * 100352 + p;
    const float* xb = x + n * 802816 + (2 * ho) * 56 + 2 * wo;
    const int ai = t >> 1;
    const int ak = (t & 1) * 8;
    const float s2 = *s2p;

    u64 acc2[8][4];

    // ---------------- Phase A: conv3 (K = 128) ----------------
    ACC_INIT();
    for (int k0 = 0; k0 < 128; k0 += 16) {
        LOAD_A_VEC(As, w3 + (coT + ai) * 128 + k0 + ak);
        const u8* xp = o2b + (k0 + krow * 8) * 784;
#pragma unroll
        for (int r = 0; r < 8; ++r)
            Bs[(krow * 8 + r) * 128 + jcol] = (float)xp[r * 784] * s2;
        GEMM_COMPUTE_STEP(As, Bs);
    }
    {
        const float s3 = *s3p;
        float inv_[8], bia_[8];
#pragma unroll
        for (int i = 0; i < 8; ++i) {
            int co = coT + ty * 8 + i;
            float iv = g3[co] / sqrtf(v3[co] + EPSBN);
            inv_[i] = iv;
            bia_[i] = b3[co] - m3[co] * iv;
        }
#pragma unroll
        for (int j = 0; j < 8; ++j)
#pragma unroll
            for (int i = 0; i < 8; ++i) {
                float y = ACCV(i, j) * inv_[i] + bia_[i];
                t3s[(tx * 8 + j) * 129 + ty * 8 + i] = fq(y, s3);
            }
    }
    __syncthreads();

    // ---------------- Phase B: conv4 shortcut (K = 256) ----------------
    ACC_INIT();
    for (int k0 = 0; k0 < 256; k0 += 16) {
        LOAD_A_VEC(As, ws + (coT + ai) * 256 + k0 + ak);
        const float* xp = xb + (k0 + krow * 8) * 3136;
#pragma unroll
        for (int r = 0; r < 8; ++r) Bs[(krow * 8 + r) * 128 + jcol] = xp[r * 3136];
        GEMM_COMPUTE_STEP(As, Bs);
    }
    {
        const float s = *ssp;
        float inv_[8], bia_[8];
#pragma unroll
        for (int i = 0; i < 8; ++i) {
            int co = coT + ty * 8 + i;
            float iv = gs[co] / sqrtf(vs[co] + EPSBN);
            inv_[i] = iv;
            bia_[i] = bs[co] - ms[co] * iv;
        }
#pragma unroll
        for (int j = 0; j < 8; ++j) {
            int jj = blockIdx.x * 128 + tx * 8 + j;
            int nn = jj / 784, pp = jj - nn * 784;
            float* op = out + nn * 401408 + (coT + ty * 8) * 784 + pp;
#pragma unroll
            for (int i = 0; i < 8; ++i) {
                float y  = ACCV(i, j) * inv_[i] + bia_[i];
                float qs = fq(y, s);
                float t3 = t3s[(tx * 8 + j) * 129 + ty * 8 + i];
                op[i * 784] = fmaxf(t3 + qs, 0.f);
            }
        }
    }
}

// ---------------------------------------------------------------------------
extern "C" void kernel_launch(void* const* d_in, const int* in_sizes, int n_in,
                              void* d_out, int out_size)
{
    const float* x  = (const float*)d_in[0];
    const float* w1 = (const float*)d_in[1];
    const float* g1 = (const float*)d_in[2];
    const float* b1 = (const float*)d_in[3];
    const float* m1 = (const float*)d_in[4];
    const float* v1 = (const float*)d_in[5];
    const float* s1 = (const float*)d_in[6];
    const float* w2 = (const float*)d_in[7];
    const float* g2 = (const float*)d_in[8];
    const float* b2 = (const float*)d_in[9];
    const float* m2 = (const float*)d_in[10];
    const float* v2 = (const float*)d_in[11];
    const float* s2 = (const float*)d_in[12];
    const float* w3 = (const float*)d_in[13];
    const float* g3 = (const float*)d_in[14];
    const float* b3 = (const float*)d_in[15];
    const float* m3 = (const float*)d_in[16];
    const float* v3 = (const float*)d_in[17];
    const float* s3 = (const float*)d_in[18];
    const float* ws = (const float*)d_in[19];
    const float* gs = (const float*)d_in[20];
    const float* bs = (const float*)d_in[21];
    const float* ms = (const float*)d_in[22];
    const float* vs = (const float*)d_in[23];
    const float* ss = (const float*)d_in[24];

    static int inited = 0;
    if (!inited) {
        cudaFuncSetAttribute(conv34_k, cudaFuncAttributeMaxDynamicSharedMemorySize, SM34);
        inited = 1;
    }

    conv1_k<<<784, 256>>>(x, w1, g1, b1, m1, v1, s1);
    conv2_k<<<196, 256>>>(w2, g2, b2, m2, v2, s2, s1);
    conv34_k<<<dim3(196, 4), 256, SM34>>>(x, w3, g3, b3, m3, v3, s3, s2,
                                          ws, gs, bs, ms, vs, ss, (float*)d_out);
}